// round 2
// baseline (speedup 1.0000x reference)
#include <cuda_runtime.h>
#include <math.h>

// Problem constants
#define TOK   8192      // B*S
#define DD    2048      // D
#define NE    64        // experts
#define KSPL  4         // K-split factor
#define DSPL  512       // d per K-split  (2048/4)
#define BM    128       // tokens per CTA
#define BK    16        // d per chunk
#define NPROB 16384     // TOK * TOPK

// Partial scores scratch: [KSPL][TOK][NE] = 8 MB
__device__ float g_part[KSPL * TOK * NE];

__global__ __launch_bounds__(256)
void gemm_amp_phase_kernel(const float* __restrict__ xr,
                           const float* __restrict__ xi,
                           const float* __restrict__ W) {
    // A tiles stored transposed [k][m] with pad to avoid bank conflicts
    __shared__ float sAa[BK][132];
    __shared__ float sAp[BK][132];
    __shared__ float sWa[BK][NE];
    __shared__ float sWp[BK][NE];

    const int tok0 = blockIdx.x * BM;
    const int ks   = blockIdx.y;
    const int tid  = threadIdx.x;
    const int tx   = tid & 15;     // n-dim
    const int ty   = tid >> 4;     // m-dim
    const int n0   = tx * 4;
    const int m0   = ty * 8;

    float acc[8][4];
#pragma unroll
    for (int i = 0; i < 8; i++)
#pragma unroll
        for (int j = 0; j < 4; j++) acc[i][j] = 0.0f;

    const int dbeg = ks * DSPL;
    for (int dc = dbeg; dc < dbeg + DSPL; dc += BK) {
        // ---- load W chunk: rows [dc, dc+16) (amp) and [2048+dc, ...) (phase)
        {
            const int k = tid >> 4;          // 0..15
            const int c = (tid & 15) << 2;   // 0..60
            *(float4*)&sWa[k][c] = *(const float4*)&W[(size_t)(dc + k) * NE + c];
            *(float4*)&sWp[k][c] = *(const float4*)&W[(size_t)(DD + dc + k) * NE + c];
        }
        // ---- load x, compute amp/phase, store transposed
#pragma unroll
        for (int r = 0; r < 2; r++) {
            const int v    = tid + 256 * r;   // 0..511
            const int t    = v >> 2;          // token 0..127
            const int dcol = (v & 3) << 2;    // 0,4,8,12
            const size_t base = (size_t)(tok0 + t) * DD + dc + dcol;
            const float4 a = *(const float4*)&xr[base];
            const float4 b = *(const float4*)&xi[base];
            float am[4], ph[4];
            am[0] = sqrtf(fmaf(a.x, a.x, b.x * b.x)); ph[0] = atan2f(b.x, a.x);
            am[1] = sqrtf(fmaf(a.y, a.y, b.y * b.y)); ph[1] = atan2f(b.y, a.y);
            am[2] = sqrtf(fmaf(a.z, a.z, b.z * b.z)); ph[2] = atan2f(b.z, a.z);
            am[3] = sqrtf(fmaf(a.w, a.w, b.w * b.w)); ph[3] = atan2f(b.w, a.w);
#pragma unroll
            for (int u = 0; u < 4; u++) {
                sAa[dcol + u][t] = am[u];
                sAp[dcol + u][t] = ph[u];
            }
        }
        __syncthreads();

        // ---- MMA: 16 k-steps, 8x4 thread tile, all LDS.128
#pragma unroll
        for (int kk = 0; kk < BK; kk++) {
            const float4 wa  = *(const float4*)&sWa[kk][n0];
            const float4 wp  = *(const float4*)&sWp[kk][n0];
            const float4 aa0 = *(const float4*)&sAa[kk][m0];
            const float4 aa1 = *(const float4*)&sAa[kk][m0 + 4];
            const float4 ap0 = *(const float4*)&sAp[kk][m0];
            const float4 ap1 = *(const float4*)&sAp[kk][m0 + 4];
            float aam[8], apm[8];
            aam[0] = aa0.x; aam[1] = aa0.y; aam[2] = aa0.z; aam[3] = aa0.w;
            aam[4] = aa1.x; aam[5] = aa1.y; aam[6] = aa1.z; aam[7] = aa1.w;
            apm[0] = ap0.x; apm[1] = ap0.y; apm[2] = ap0.z; apm[3] = ap0.w;
            apm[4] = ap1.x; apm[5] = ap1.y; apm[6] = ap1.z; apm[7] = ap1.w;
#pragma unroll
            for (int i = 0; i < 8; i++) {
                acc[i][0] = fmaf(aam[i], wa.x, fmaf(apm[i], wp.x, acc[i][0]));
                acc[i][1] = fmaf(aam[i], wa.y, fmaf(apm[i], wp.y, acc[i][1]));
                acc[i][2] = fmaf(aam[i], wa.z, fmaf(apm[i], wp.z, acc[i][2]));
                acc[i][3] = fmaf(aam[i], wa.w, fmaf(apm[i], wp.w, acc[i][3]));
            }
        }
        __syncthreads();
    }

    // ---- write partial scores
    float* dst = g_part + ((size_t)ks * TOK + tok0) * NE;
#pragma unroll
    for (int i = 0; i < 8; i++) {
        float4 o = make_float4(acc[i][0], acc[i][1], acc[i][2], acc[i][3]);
        *(float4*)&dst[(size_t)(m0 + i) * NE + n0] = o;
    }
}

__global__ __launch_bounds__(256)
void topk_kernel(const float* __restrict__ bvec, float* __restrict__ out) {
    const int gtid = blockIdx.x * blockDim.x + threadIdx.x;
    const int tok  = gtid >> 5;
    const int lane = threadIdx.x & 31;
    if (tok >= TOK) return;

    // each lane owns experts 2*lane and 2*lane+1; sum the 4 K-split partials
    float s0 = 0.0f, s1 = 0.0f;
#pragma unroll
    for (int ks = 0; ks < KSPL; ks++) {
        const float2 v = *(const float2*)&g_part[((size_t)ks * TOK + tok) * NE + lane * 2];
        s0 += v.x; s1 += v.y;
    }
    s0 += bvec[2 * lane];
    s1 += bvec[2 * lane + 1];

    // top-1 with jax tie-break (lower index on equal values)
    float bv; int bi;
    if (s1 > s0) { bv = s1; bi = 2 * lane + 1; } else { bv = s0; bi = 2 * lane; }
#pragma unroll
    for (int off = 16; off > 0; off >>= 1) {
        const float ov = __shfl_down_sync(0xffffffffu, bv, off);
        const int   oi = __shfl_down_sync(0xffffffffu, bi, off);
        if (ov > bv || (ov == bv && oi < bi)) { bv = ov; bi = oi; }
    }
    bv = __shfl_sync(0xffffffffu, bv, 0);
    bi = __shfl_sync(0xffffffffu, bi, 0);

    // top-2: exclude bi
    const float NEG = -3.4e38f;
    float t0 = (2 * lane     == bi) ? NEG : s0;
    float t1 = (2 * lane + 1 == bi) ? NEG : s1;
    float cv; int ci;
    if (t1 > t0) { cv = t1; ci = 2 * lane + 1; } else { cv = t0; ci = 2 * lane; }
#pragma unroll
    for (int off = 16; off > 0; off >>= 1) {
        const float ov = __shfl_down_sync(0xffffffffu, cv, off);
        const int   oi = __shfl_down_sync(0xffffffffu, ci, off);
        if (ov > cv || (ov == cv && oi < ci)) { cv = ov; ci = oi; }
    }

    if (lane == 0) {
        // renormalized top-2 softmax probs: denominator cancels, max = bv
        const float r  = expf(cv - bv);          // <= 1
        const float dn = 1.0f + r;
        out[tok * 2]            = 1.0f / dn;
        out[tok * 2 + 1]        = r / dn;
        out[NPROB + tok * 2]     = (float)bi;
        out[NPROB + tok * 2 + 1] = (float)ci;
    }
}

extern "C" void kernel_launch(void* const* d_in, const int* in_sizes, int n_in,
                              void* d_out, int out_size) {
    const float* xr = (const float*)d_in[0];   // x_real [4,2048,2048]
    const float* xi = (const float*)d_in[1];   // x_imag [4,2048,2048]
    const float* W  = (const float*)d_in[2];   // [4096, 64]
    const float* b  = (const float*)d_in[3];   // [64]
    float* out = (float*)d_out;                // [16384 probs][16384 indices]

    dim3 grid1(TOK / BM, KSPL);
    gemm_amp_phase_kernel<<<grid1, 256>>>(xr, xi, W);
    topk_kernel<<<TOK * 32 / 256, 256>>>(b, out);
}

// round 3
// speedup vs baseline: 1.1069x; 1.1069x over previous
#include <cuda_runtime.h>
#include <math.h>

// Problem constants
#define TOK   8192      // B*S
#define DD    2048      // D
#define NE    64        // experts
#define KSPL  9         // K-split factor (576 CTAs ~= 3.9 waves of 148 SMs)
#define NCHUNK 128      // 2048 / 16 chunks
#define BM    128       // tokens per CTA
#define BK    16        // d per chunk
#define NPROB 16384     // TOK * TOPK
#define ROWPAD 132      // padded A row (floats)

// Partial scores scratch: [KSPL][TOK][NE] = 18.9 MB
__device__ float g_part[KSPL * TOK * NE];

typedef unsigned long long u64;

__device__ __forceinline__ u64 ffma2(u64 a, u64 b, u64 c) {
    u64 d;
    asm("fma.rn.f32x2 %0, %1, %2, %3;" : "=l"(d) : "l"(a), "l"(b), "l"(c));
    return d;
}
__device__ __forceinline__ u64 dup2(float x) {
    u64 d;
    asm("mov.b64 %0, {%1, %1};" : "=l"(d) : "f"(x));
    return d;
}
__device__ __forceinline__ void lds_2x64(u64& a, u64& b, unsigned saddr) {
    asm volatile("ld.shared.v2.b64 {%0, %1}, [%2];" : "=l"(a), "=l"(b) : "r"(saddr));
}
__device__ __forceinline__ void unpack2(float& lo, float& hi, u64 v) {
    asm("mov.b64 {%0, %1}, %2;" : "=f"(lo), "=f"(hi) : "l"(v));
}

__global__ __launch_bounds__(128, 4)
void gemm_amp_phase_kernel(const float* __restrict__ xr,
                           const float* __restrict__ xi,
                           const float* __restrict__ W) {
    // A tiles transposed [k][m] (pad 132 floats/row), W tiles [k][n]
    __shared__ float sAa[BK][ROWPAD];
    __shared__ float sAp[BK][ROWPAD];
    __shared__ float sWa[BK][NE];
    __shared__ float sWp[BK][NE];

    const int tok0 = blockIdx.x * BM;
    const int ks   = blockIdx.y;
    const int tid  = threadIdx.x;
    // warp = m-major: lanes span m (16 positions), share n within 16-lane halves
    const int my = tid & 15;      // m-group 0..15
    const int nx = tid >> 4;      // n-group 0..7
    const int m0 = my * 8;
    const int n0 = nx * 8;

    // acc[n][mpair] as packed f32x2 (pair = two adjacent tokens)
    u64 acc[8][4];
#pragma unroll
    for (int n = 0; n < 8; n++)
#pragma unroll
        for (int p = 0; p < 4; p++) acc[n][p] = 0ull;

    // chunk range for this K-split: 128 chunks over 9 splits (15,15,14,...)
    const int base = ks * (NCHUNK / KSPL) + min(ks, NCHUNK % KSPL);
    const int cnt  = NCHUNK / KSPL + (ks < (NCHUNK % KSPL) ? 1 : 0);

    const unsigned sAa_base = (unsigned)__cvta_generic_to_shared(&sAa[0][0]);
    const unsigned sAp_base = (unsigned)__cvta_generic_to_shared(&sAp[0][0]);

    for (int c = base; c < base + cnt; c++) {
        const int dc = c * BK;
        // ---- load W chunk rows [dc,dc+16) amp / [2048+dc,..) phase
#pragma unroll
        for (int j = 0; j < 2; j++) {
            const int v   = tid + 128 * j;
            const int row = v >> 4;
            const int col = (v & 15) << 2;
            *(float4*)&sWa[row][col] = *(const float4*)&W[(size_t)(dc + row) * NE + col];
            *(float4*)&sWp[row][col] = *(const float4*)&W[(size_t)(DD + dc + row) * NE + col];
        }
        // ---- load x, compute amp/phase, store transposed
#pragma unroll
        for (int r = 0; r < 4; r++) {
            const int v    = tid + 128 * r;   // 0..511
            const int t    = v >> 2;          // token 0..127
            const int dcol = (v & 3) << 2;    // 0,4,8,12
            const size_t gbase = (size_t)(tok0 + t) * DD + dc + dcol;
            const float4 a = *(const float4*)&xr[gbase];
            const float4 b = *(const float4*)&xi[gbase];
            float am[4], ph[4];
            am[0] = sqrtf(fmaf(a.x, a.x, b.x * b.x)); ph[0] = atan2f(b.x, a.x);
            am[1] = sqrtf(fmaf(a.y, a.y, b.y * b.y)); ph[1] = atan2f(b.y, a.y);
            am[2] = sqrtf(fmaf(a.z, a.z, b.z * b.z)); ph[2] = atan2f(b.z, a.z);
            am[3] = sqrtf(fmaf(a.w, a.w, b.w * b.w)); ph[3] = atan2f(b.w, a.w);
#pragma unroll
            for (int u = 0; u < 4; u++) {
                sAa[dcol + u][t] = am[u];
                sAp[dcol + u][t] = ph[u];
            }
        }
        __syncthreads();

        // ---- MMA: 16 k-steps, 8m x 8n per thread, packed f32x2 along m
#pragma unroll
        for (int kk = 0; kk < BK; kk++) {
            u64 aa[4], ap[4];
            const unsigned off = (unsigned)((kk * ROWPAD + m0) * 4);
            lds_2x64(aa[0], aa[1], sAa_base + off);
            lds_2x64(aa[2], aa[3], sAa_base + off + 16);
            lds_2x64(ap[0], ap[1], sAp_base + off);
            lds_2x64(ap[2], ap[3], sAp_base + off + 16);
            const float4 wa0 = *(const float4*)&sWa[kk][n0];
            const float4 wa1 = *(const float4*)&sWa[kk][n0 + 4];
            const float4 wp0 = *(const float4*)&sWp[kk][n0];
            const float4 wp1 = *(const float4*)&sWp[kk][n0 + 4];
            const float wav[8] = {wa0.x, wa0.y, wa0.z, wa0.w, wa1.x, wa1.y, wa1.z, wa1.w};
            const float wpv[8] = {wp0.x, wp0.y, wp0.z, wp0.w, wp1.x, wp1.y, wp1.z, wp1.w};
#pragma unroll
            for (int n = 0; n < 8; n++) {
                const u64 wd = dup2(wav[n]);
                const u64 pd = dup2(wpv[n]);
#pragma unroll
                for (int p = 0; p < 4; p++) {
                    acc[n][p] = ffma2(aa[p], wd, ffma2(ap[p], pd, acc[n][p]));
                }
            }
        }
        __syncthreads();
    }

    // ---- write partial scores: unpack pairs, assemble per-token float4s
    float* dst = g_part + ((size_t)ks * TOK + tok0) * NE;
#pragma unroll
    for (int p = 0; p < 4; p++) {
        float e[8], o[8];
#pragma unroll
        for (int n = 0; n < 8; n++) unpack2(e[n], o[n], acc[n][p]);
        const int te = m0 + 2 * p;
        *(float4*)&dst[(size_t)te * NE + n0]           = make_float4(e[0], e[1], e[2], e[3]);
        *(float4*)&dst[(size_t)te * NE + n0 + 4]       = make_float4(e[4], e[5], e[6], e[7]);
        *(float4*)&dst[(size_t)(te + 1) * NE + n0]     = make_float4(o[0], o[1], o[2], o[3]);
        *(float4*)&dst[(size_t)(te + 1) * NE + n0 + 4] = make_float4(o[4], o[5], o[6], o[7]);
    }
}

__global__ __launch_bounds__(256)
void topk_kernel(const float* __restrict__ bvec, float* __restrict__ out) {
    const int gtid = blockIdx.x * blockDim.x + threadIdx.x;
    const int tok  = gtid >> 5;
    const int lane = threadIdx.x & 31;
    if (tok >= TOK) return;

    // each lane owns experts 2*lane, 2*lane+1; sum the KSPL partials
    float s0 = 0.0f, s1 = 0.0f;
#pragma unroll
    for (int ks = 0; ks < KSPL; ks++) {
        const float2 v = *(const float2*)&g_part[((size_t)ks * TOK + tok) * NE + lane * 2];
        s0 += v.x; s1 += v.y;
    }
    s0 += bvec[2 * lane];
    s1 += bvec[2 * lane + 1];

    // top-1 with jax tie-break (lower index wins on equal values)
    float bv; int bi;
    if (s1 > s0) { bv = s1; bi = 2 * lane + 1; } else { bv = s0; bi = 2 * lane; }
#pragma unroll
    for (int off = 16; off > 0; off >>= 1) {
        const float ov = __shfl_down_sync(0xffffffffu, bv, off);
        const int   oi = __shfl_down_sync(0xffffffffu, bi, off);
        if (ov > bv || (ov == bv && oi < bi)) { bv = ov; bi = oi; }
    }
    bv = __shfl_sync(0xffffffffu, bv, 0);
    bi = __shfl_sync(0xffffffffu, bi, 0);

    // top-2: exclude bi
    const float NEG = -3.4e38f;
    float t0 = (2 * lane     == bi) ? NEG : s0;
    float t1 = (2 * lane + 1 == bi) ? NEG : s1;
    float cv; int ci;
    if (t1 > t0) { cv = t1; ci = 2 * lane + 1; } else { cv = t0; ci = 2 * lane; }
#pragma unroll
    for (int off = 16; off > 0; off >>= 1) {
        const float ov = __shfl_down_sync(0xffffffffu, cv, off);
        const int   oi = __shfl_down_sync(0xffffffffu, ci, off);
        if (ov > cv || (ov == cv && oi < ci)) { cv = ov; ci = oi; }
    }

    if (lane == 0) {
        // renormalized top-2 softmax: global denominator cancels, max = bv
        const float r  = expf(cv - bv);
        const float dn = 1.0f + r;
        out[tok * 2]             = 1.0f / dn;
        out[tok * 2 + 1]         = r / dn;
        out[NPROB + tok * 2]     = (float)bi;
        out[NPROB + tok * 2 + 1] = (float)ci;
    }
}

extern "C" void kernel_launch(void* const* d_in, const int* in_sizes, int n_in,
                              void* d_out, int out_size) {
    const float* xr = (const float*)d_in[0];   // x_real [4,2048,2048]
    const float* xi = (const float*)d_in[1];   // x_imag [4,2048,2048]
    const float* W  = (const float*)d_in[2];   // [4096, 64]
    const float* b  = (const float*)d_in[3];   // [64]
    float* out = (float*)d_out;                // [16384 probs][16384 indices]

    dim3 grid1(TOK / BM, KSPL);
    gemm_amp_phase_kernel<<<grid1, 128>>>(xr, xi, W);
    topk_kernel<<<TOK * 32 / 256, 256>>>(b, out);
}